// round 6
// baseline (speedup 1.0000x reference)
#include <cuda_runtime.h>

#define CNUM 19
#define HWD (512*512)
#define BATCH 8
#define NPIX (BATCH*HWD)
#define NP4 (NPIX/4)
#define CH4 (HWD/4)            // channel stride in float4 units
#define NBINS (CNUM*CNUM)      // 361
#define INP_ELEMS (BATCH*CNUM*HWD)   // 39,845,888

// Output written as FLOAT32. Counts (<= 2M) are exactly representable.
__global__ void zero_out_kernel(float* __restrict__ out)
{
    int i = blockIdx.x * blockDim.x + threadIdx.x;
    if (i < NBINS) out[i] = 0.0f;
}

__global__ void __launch_bounds__(256)
confmat_kernel(const float* __restrict__ inp,
               const int*   __restrict__ tgt,
               float*       __restrict__ out)
{
    __shared__ int hist[NBINS];
    for (int i = threadIdx.x; i < NBINS; i += blockDim.x) hist[i] = 0;
    __syncthreads();

    const int stride = gridDim.x * blockDim.x;
    for (int p4 = blockIdx.x * blockDim.x + threadIdx.x; p4 < NP4; p4 += stride) {
        const int p  = p4 * 4;           // 4 consecutive pixels, same batch (HWD % 4 == 0)
        const int b  = p / HWD;
        const int hw = p % HWD;
        const float4* base = reinterpret_cast<const float4*>(
            inp + (long long)b * CNUM * HWD + hw);

        float4 m = base[0];
        int ax = 0, ay = 0, az = 0, aw = 0;
        #pragma unroll
        for (int c = 1; c < CNUM; c++) {
            float4 v = __ldg(&base[c * CH4]);
            if (v.x > m.x) { m.x = v.x; ax = c; }
            if (v.y > m.y) { m.y = v.y; ay = c; }
            if (v.z > m.z) { m.z = v.z; az = c; }
            if (v.w > m.w) { m.w = v.w; aw = c; }
        }

        const int4 t = *reinterpret_cast<const int4*>(tgt + p);
        // Clamp bins — crash-proof against out-of-spec targets, exact for 0..18.
        int i0 = t.x * CNUM + ax;  i0 = min(max(i0, 0), NBINS - 1);
        int i1 = t.y * CNUM + ay;  i1 = min(max(i1, 0), NBINS - 1);
        int i2 = t.z * CNUM + az;  i2 = min(max(i2, 0), NBINS - 1);
        int i3 = t.w * CNUM + aw;  i3 = min(max(i3, 0), NBINS - 1);
        atomicAdd(&hist[i0], 1);
        atomicAdd(&hist[i1], 1);
        atomicAdd(&hist[i2], 1);
        atomicAdd(&hist[i3], 1);
    }
    __syncthreads();

    // Flush per-block histogram to global as FLOAT atomics (counts exact in f32).
    for (int i = threadIdx.x; i < NBINS; i += blockDim.x) {
        const int v = hist[i];
        if (v) atomicAdd(&out[i], (float)v);
    }
}

extern "C" void kernel_launch(void* const* d_in, const int* in_sizes, int n_in,
                              void* d_out, int out_size)
{
    // Identify inputs by size (element counts or byte counts both accepted).
    const float* inp = nullptr;
    const int*   tgt = nullptr;
    for (int i = 0; i < n_in; i++) {
        const long long s = in_sizes[i];
        if (s == (long long)INP_ELEMS || s == (long long)INP_ELEMS * 4)
            inp = (const float*)d_in[i];
        else if (s == (long long)NPIX || s == (long long)NPIX * 4)
            tgt = (const int*)d_in[i];
    }
    if (!inp || !tgt) {
        int i_big = -1, i_second = -1;
        for (int i = 0; i < n_in; i++)
            if (i_big < 0 || in_sizes[i] > in_sizes[i_big]) i_big = i;
        for (int i = 0; i < n_in; i++) {
            if (i == i_big || in_sizes[i] <= 16) continue;
            if (i_second < 0 || in_sizes[i] > in_sizes[i_second]) i_second = i;
        }
        if (!inp && i_big >= 0)    inp = (const float*)d_in[i_big];
        if (!tgt && i_second >= 0) tgt = (const int*)d_in[i_second];
        if (!inp && n_in > 0) inp = (const float*)d_in[0];
        if (!tgt && n_in > 1) tgt = (const int*)d_in[1];
    }

    float* out = (float*)d_out;
    (void)out_size;  // zero exactly NBINS elements (safe under any units)

    zero_out_kernel<<<2, 256>>>(out);
    if (inp && tgt) {
        confmat_kernel<<<592, 256>>>(inp, tgt, out);
    }
}